// round 16
// baseline (speedup 1.0000x reference)
#include <cuda_runtime.h>
#include <cuda_fp16.h>
#include <math.h>
#include <stdint.h>

#define B_ 32
#define T_ 128
#define E_ 512
#define H_ 256
#define V_ 32000
#define G_ 1024  // 4*H

// ---------------- scratch (device globals; no allocations) ----------------
__device__ float g_bcat[G_];             // [4H]
__device__ float g_xproj[T_ * B_ * G_];  // [T][B][4H] 16 MB
__device__ __half g_Xhi[T_ * B_ * E_];   // gathered embed split (fp16), 4 MB
__device__ __half g_Xlo[T_ * B_ * E_];
__device__ __half g_Utf[G_ * E_];        // U^T single fp16, [G][E] 1 MB
__device__ __half g_Af[B_ * T_ * H_];    // hs single fp16, [B*T][H] 2 MB
__device__ __half g_Btf[V_ * H_];        // W_hy^T single fp16, [V][H] 16 MB

// ======================= PTX helpers (sm_90-base only) =====================
__device__ __forceinline__ uint32_t smem_u32(const void* p) {
    uint32_t a;
    asm("{ .reg .u64 t; cvta.to.shared.u64 t, %1; cvt.u32.u64 %0, t; }"
        : "=r"(a) : "l"(p));
    return a;
}

__device__ __forceinline__ void cp_async16(uint32_t saddr, const void* gaddr) {
    asm volatile("cp.async.cg.shared.global [%0], [%1], 16;"
                 :: "r"(saddr), "l"(gaddr) : "memory");
}
__device__ __forceinline__ void cp_commit() {
    asm volatile("cp.async.commit_group;" ::: "memory");
}
template <int N>
__device__ __forceinline__ void cp_wait() {
    asm volatile("cp.async.wait_group %0;" :: "n"(N) : "memory");
}

__device__ __forceinline__ void ldsm_x4(uint32_t& r0, uint32_t& r1,
                                        uint32_t& r2, uint32_t& r3, uint32_t a) {
    asm volatile("ldmatrix.sync.aligned.m8n8.x4.shared.b16 {%0,%1,%2,%3}, [%4];"
                 : "=r"(r0), "=r"(r1), "=r"(r2), "=r"(r3) : "r"(a));
}
__device__ __forceinline__ void ldsm_x2(uint32_t& r0, uint32_t& r1, uint32_t a) {
    asm volatile("ldmatrix.sync.aligned.m8n8.x2.shared.b16 {%0,%1}, [%2];"
                 : "=r"(r0), "=r"(r1) : "r"(a));
}

__device__ __forceinline__ void mma_f16(float* d, const uint32_t* a,
                                        const uint32_t* b) {
    asm volatile(
        "mma.sync.aligned.m16n8k16.row.col.f32.f16.f16.f32 "
        "{%0,%1,%2,%3}, {%4,%5,%6,%7}, {%8,%9}, {%0,%1,%2,%3};"
        : "+f"(d[0]), "+f"(d[1]), "+f"(d[2]), "+f"(d[3])
        : "r"(a[0]), "r"(a[1]), "r"(a[2]), "r"(a[3]), "r"(b[0]), "r"(b[1]));
}

#define CLUSTER_SYNC() do { \
    asm volatile("barrier.cluster.arrive.aligned;" ::: "memory"); \
    asm volatile("barrier.cluster.wait.aligned;" ::: "memory"); \
} while (0)

__device__ __forceinline__ uint32_t mapa_cluster(uint32_t local, uint32_t rank) {
    uint32_t r;
    asm volatile("mapa.shared::cluster.u32 %0, %1, %2;" : "=r"(r) : "r"(local), "r"(rank));
    return r;
}
__device__ __forceinline__ void st_cluster_f32(uint32_t addr, float v) {
    asm volatile("st.shared::cluster.f32 [%0], %1;" :: "r"(addr), "f"(v) : "memory");
}

// fast NaN-safe sigmoid / tanh via MUFU.EX2 (rel err ~2^-22)
__device__ __forceinline__ float fast_sigmoid(float x) {
    return 1.f / (1.f + __expf(-x));
}
__device__ __forceinline__ float fast_tanh(float x) {
    return 1.f - 2.f / (1.f + __expf(2.f * x));
}

// ---------------- pack bias only ----------------
__global__ void packb_kernel(const float* __restrict__ bi, const float* __restrict__ bf,
                             const float* __restrict__ bg, const float* __restrict__ bo)
{
    int i = blockIdx.x * blockDim.x + threadIdx.x;
    if (i < G_) {
        int g = i / H_, jj = i % H_;
        const float* bb = (g == 0) ? bi : (g == 1) ? bf : (g == 2) ? bg : bo;
        g_bcat[i] = bb[jj];
    }
}

// --------- transpose W_hy [H][V] -> Btf [V][H] single fp16 ---------
__global__ void convW_kernel(const float* __restrict__ W_hy)
{
    __shared__ float tl[32][33];
    int v0 = blockIdx.x * 32, k0 = blockIdx.y * 32;
    int tx = threadIdx.x, ty = threadIdx.y;
#pragma unroll
    for (int i = 0; i < 4; i++) {
        int k = ty + i * 8;
        tl[k][tx] = W_hy[(size_t)(k0 + k) * V_ + v0 + tx];
    }
    __syncthreads();
#pragma unroll
    for (int i = 0; i < 4; i++) {
        int vr = ty + i * 8;
        g_Btf[(size_t)(v0 + vr) * H_ + k0 + tx] = __float2half(tl[tx][vr]);
    }
}

// --------- transpose gate U [E][H] -> Utf [G][E] single fp16 ----------
__global__ void convU_kernel(const float* __restrict__ Ui, const float* __restrict__ Uf,
                             const float* __restrict__ Ug, const float* __restrict__ Uo)
{
    __shared__ float tl[32][33];
    const int gate = blockIdx.z;
    const float* U = (gate == 0) ? Ui : (gate == 1) ? Uf : (gate == 2) ? Ug : Uo;
    int h0 = blockIdx.x * 32, e0 = blockIdx.y * 32;
    int tx = threadIdx.x, ty = threadIdx.y;
#pragma unroll
    for (int i = 0; i < 4; i++) {
        int e = ty + i * 8;
        tl[e][tx] = U[(size_t)(e0 + e) * H_ + h0 + tx];
    }
    __syncthreads();
#pragma unroll
    for (int i = 0; i < 4; i++) {
        int hr = ty + i * 8;
        g_Utf[(size_t)(gate * H_ + h0 + hr) * E_ + e0 + tx] =
            __float2half(tl[tx][hr]);
    }
}

// --------- gather embed rows + fp16-split: X[r=t*B+b][E] ----------
__global__ void gatherX_kernel(const float* __restrict__ embed,
                               const int* __restrict__ xind)
{
    const int r = blockIdx.x;          // 0..T*B-1, r = t*B + b
    const int t = r / B_, b = r % B_;
    const float* src = embed + (size_t)xind[b * T_ + t] * E_;
    for (int i = threadIdx.x * 4; i < E_; i += blockDim.x * 4) {
        float4 v = *reinterpret_cast<const float4*>(src + i);
        __half h0 = __float2half(v.x);
        __half h1 = __float2half(v.y);
        __half h2 = __float2half(v.z);
        __half h3 = __float2half(v.w);
        __half2 hi01 = {h0, h1}, hi23 = {h2, h3};
        __half2 lo01 = {__float2half(v.x - __half2float(h0)),
                        __float2half(v.y - __half2float(h1))};
        __half2 lo23 = {__float2half(v.z - __half2float(h2)),
                        __float2half(v.w - __half2float(h3))};
        *reinterpret_cast<__half2*>(g_Xhi + (size_t)r * E_ + i)     = hi01;
        *reinterpret_cast<__half2*>(g_Xhi + (size_t)r * E_ + i + 2) = hi23;
        *reinterpret_cast<__half2*>(g_Xlo + (size_t)r * E_ + i)     = lo01;
        *reinterpret_cast<__half2*>(g_Xlo + (size_t)r * E_ + i + 2) = lo23;
    }
}

// ===== LSTM recurrence v7: 512 threads/CTA (FFMA issue halved) ======
// Cluster of 8 CTAs, 2 batches. CTA rank owns h-slice [rank*32, rank*32+32)
// -> 128 z-cols. 512 threads: kg = tid>>5 (16-k block 0..15), cg = tid&31
// (4 consecutive cols). wreg[16] float4. Per thread/step: 8 LDS.128,
// 128 FFMA in 8 indep chains.
#define CL_C 8
#define NB 2
#define SCAN_THREADS 512

__global__ void __cluster_dims__(CL_C, 1, 1) __launch_bounds__(SCAN_THREADS, 1)
lstm_scan_v7(const float* __restrict__ Wi, const float* __restrict__ Wf,
             const float* __restrict__ Wg, const float* __restrict__ Wo)
{
    __shared__ float h_s[2 * NB * 256];      // [buf][batch][256]
    __shared__ float zp_s[16 * NB * 128];    // [kg][batch][col]

    const int tid = threadIdx.x;
    uint32_t rank;
    asm("mov.u32 %0, %%cluster_ctarank;" : "=r"(rank));
    const int cid = blockIdx.x / CL_C;

    const int kg = tid >> 5;          // 16-k block 0..15
    const int cg = tid & 31;          // 4-col group 0..31
    const int gate0 = cg >> 3;        // gate of these 4 cols
    const int s0    = (cg & 7) * 4;   // slice col base

    const float* wsel = (gate0 == 0) ? Wi : (gate0 == 1) ? Wf
                       : (gate0 == 2) ? Wg : Wo;
    float4 wreg[16];
    {
        const float* wp = wsel + (size_t)(kg * 16) * H_ + (int)rank * 32 + s0;
#pragma unroll
        for (int k = 0; k < 16; k++)
            wreg[k] = *reinterpret_cast<const float4*>(wp + (size_t)k * H_);
    }

    for (int i = tid; i < 2 * NB * 256; i += SCAN_THREADS) h_s[i] = 0.f;
    CLUSTER_SYNC();

    const int bgl0 = cid * NB;

    const int gb = tid >> 5;   // batch (valid when tid<64)
    const int gs = tid & 31;   // slice col
    float c_reg = 0.f;

    for (int t = 0; t < T_; t++) {
        const int p = t & 1;

        float xpi = 0.f, xpf = 0.f, xpg = 0.f, xpo = 0.f;
        if (tid < 64) {
            const float* xb = g_xproj + (size_t)(t * B_ + bgl0 + gb) * G_ +
                              (int)rank * 32 + gs;
            xpi = xb[0];
            xpf = xb[H_];
            xpg = xb[2 * H_];
            xpo = xb[3 * H_];
        }

        // ---- dot: 4 cols x 2 batches over this thread's 16-k block ----
        const float* h0p = h_s + p * (NB * 256) + kg * 16;
        const float* h1p = h0p + 256;
        float4 a0 = make_float4(0.f, 0.f, 0.f, 0.f);
        float4 a1 = make_float4(0.f, 0.f, 0.f, 0.f);
#pragma unroll
        for (int i = 0; i < 4; i++) {
            float4 v0 = *reinterpret_cast<const float4*>(h0p + i * 4);
            float4 v1 = *reinterpret_cast<const float4*>(h1p + i * 4);
#pragma unroll
            for (int kk = 0; kk < 4; kk++) {
                float4 w = wreg[i * 4 + kk];
                float e0 = (kk == 0) ? v0.x : (kk == 1) ? v0.y : (kk == 2) ? v0.z : v0.w;
                float e1 = (kk == 0) ? v1.x : (kk == 1) ? v1.y : (kk == 2) ? v1.z : v1.w;
                a0.x += e0 * w.x; a0.y += e0 * w.y; a0.z += e0 * w.z; a0.w += e0 * w.w;
                a1.x += e1 * w.x; a1.y += e1 * w.y; a1.z += e1 * w.z; a1.w += e1 * w.w;
            }
        }
        *reinterpret_cast<float4*>(zp_s + (kg * NB + 0) * 128 + cg * 4) = a0;
        *reinterpret_cast<float4*>(zp_s + (kg * NB + 1) * 128 + cg * 4) = a1;
        __syncthreads();

        if (tid < 64) {
            float zi = xpi, zf = xpf, zg = xpg, zo = xpo;
#pragma unroll
            for (int q = 0; q < 16; q++) {
                const float* base = zp_s + (q * NB + gb) * 128;
                zi += base[gs];
                zf += base[32 + gs];
                zg += base[64 + gs];
                zo += base[96 + gs];
            }
            float ig = fast_sigmoid(zi);
            float fg = fast_sigmoid(zf);
            float gv = fast_tanh(zg);
            float og = fast_sigmoid(zo);
            c_reg = fg * c_reg + ig * gv;
            float h = og * fast_tanh(c_reg);

            // single fp16 output for logits GEMM
            int bg = bgl0 + gb;
            g_Af[((size_t)bg * T_ + t) * H_ + rank * 32 + gs] = __float2half(h);

            const int q2 = p ^ 1;
            uint32_t la = smem_u32(h_s + q2 * (NB * 256) + gb * 256 +
                                   (int)rank * 32 + gs);
#pragma unroll
            for (int rk = 0; rk < CL_C; rk++)
                st_cluster_f32(mapa_cluster(la, (uint32_t)rk), h);
        }
        CLUSTER_SYNC();
    }
}

// ======== HGEMM fp16, 3-stage cp.async ring ==========
// MODE 0 (2-term A): g_xproj = (Xhi+Xlo) @ Utf^T + g_bcat   (K=512)
// MODE 1 (1-term A): out     = Af @ Btf^T + b_y             (K=256)
// BM=BN=128, BK=32, 8 warps 2x4, m16n8k16 f16, occ 2.
#define BK 32
#define SROW 40                       // padded row stride (fp16 elems) = 80B
#define TILE_SB (128 * SROW * 2)      // 10240 B per matrix per stage
#define NBUF 3

template <int MODE>
__global__ __launch_bounds__(256, 2) void hgemm_kernel(
    const float* __restrict__ bias_ext, float* __restrict__ out_ext)
{
    constexpr int NDIM = (MODE == 0) ? G_ : V_;
    constexpr int KDIM = (MODE == 0) ? E_ : H_;
    constexpr int NSTG = KDIM / BK;
    constexpr int NA   = (MODE == 0) ? 2 : 1;        // A terms
    constexpr int NMAT = NA + 1;
    constexpr int STG  = NMAT * TILE_SB;             // stage bytes

    extern __shared__ char smem[];
    const uint32_t sb = smem_u32(smem);
    const int tid  = threadIdx.x;
    const int lane = tid & 31;
    const int wid  = tid >> 5;
    const int wm   = wid >> 2;
    const int wn   = wid & 3;

    const int row0 = blockIdx.y * 128;
    const int col0 = blockIdx.x * 128;

    const float* bias = (MODE == 0) ? g_bcat  : bias_ext;
    float*       out  = (MODE == 0) ? g_xproj : out_ext;

    const int ld_r   = tid >> 2;
    const int ld_seg = tid & 3;
    const __half* gsrc[NMAT];
    if (MODE == 0) {
        gsrc[0] = g_Xhi + (size_t)row0 * KDIM;
        gsrc[1] = g_Xlo + (size_t)row0 * KDIM;
        gsrc[NA] = g_Utf + (size_t)col0 * KDIM;
    } else {
        gsrc[0] = g_Af + (size_t)row0 * KDIM;
        gsrc[NA] = g_Btf + (size_t)col0 * KDIM;
    }

    float acc[4][4][4];
#pragma unroll
    for (int i = 0; i < 4; i++)
#pragma unroll
        for (int j = 0; j < 4; j++)
#pragma unroll
            for (int r = 0; r < 4; r++) acc[i][j][r] = 0.f;

    // prologue: stages 0 and 1
#pragma unroll
    for (int ps = 0; ps < 2; ps++) {
#pragma unroll
        for (int m = 0; m < NMAT; m++)
#pragma unroll
            for (int h = 0; h < 2; h++) {
                int r = ld_r + h * 64;
                uint32_t sa = sb + ps * STG + m * TILE_SB +
                              r * (SROW * 2) + ld_seg * 16;
                cp_async16(sa, gsrc[m] + (size_t)r * KDIM + ps * BK + ld_seg * 8);
            }
        cp_commit();
    }

    for (int s = 0; s < NSTG; s++) {
        if (s + 1 < NSTG) cp_wait<1>(); else cp_wait<0>();
        __syncthreads();

        if (s + 2 < NSTG) {
            uint32_t bufo = (uint32_t)((s + 2) % NBUF) * STG;
            int kofs = (s + 2) * BK;
#pragma unroll
            for (int m = 0; m < NMAT; m++)
#pragma unroll
                for (int h = 0; h < 2; h++) {
                    int r = ld_r + h * 64;
                    uint32_t sa = sb + bufo + m * TILE_SB +
                                  r * (SROW * 2) + ld_seg * 16;
                    cp_async16(sa, gsrc[m] + (size_t)r * KDIM + kofs + ld_seg * 8);
                }
            cp_commit();
        }

        const uint32_t base = sb + (uint32_t)(s % NBUF) * STG;
        const uint32_t sA0 = base;
        const uint32_t sA1 = base + TILE_SB;             // valid when NA==2
        const uint32_t sBf = base + NA * TILE_SB;

#pragma unroll
        for (int kk = 0; kk < 2; kk++) {
            uint32_t bf[4][2];
            const int b_row_l = (lane & 7);
            const int b_col   = kk * 16 + ((lane >> 3) & 1) * 8;
#pragma unroll
            for (int nt = 0; nt < 4; nt++) {
                int r = wn * 32 + nt * 8 + b_row_l;
                uint32_t off = (uint32_t)(r * (SROW * 2) + b_col * 2);
                ldsm_x2(bf[nt][0], bf[nt][1], sBf + off);
            }
            const int a_row_l = (lane & 15);
            const int a_col   = kk * 16 + (lane >> 4) * 8;
#pragma unroll
            for (int mt = 0; mt < 4; mt++) {
                int r = wm * 64 + mt * 16 + a_row_l;
                uint32_t off = (uint32_t)(r * (SROW * 2) + a_col * 2);
                uint32_t a0[4];
                ldsm_x4(a0[0], a0[1], a0[2], a0[3], sA0 + off);
                if (NA == 2) {
                    uint32_t a1[4];
                    ldsm_x4(a1[0], a1[1], a1[2], a1[3], sA1 + off);
#pragma unroll
                    for (int nt = 0; nt < 4; nt++) {
                        mma_f16(acc[mt][nt], a0, bf[nt]);
                        mma_f16(acc[mt][nt], a1, bf[nt]);
                    }
                } else {
#pragma unroll
                    for (int nt = 0; nt < 4; nt++)
                        mma_f16(acc[mt][nt], a0, bf[nt]);
                }
            }
        }
    }

    __syncthreads();
    const int er = lane >> 2;
    const int ec = (lane & 3) * 2;
#pragma unroll
    for (int mt = 0; mt < 4; mt++) {
#pragma unroll
        for (int nt = 0; nt < 4; nt++) {
            int col = col0 + wn * 32 + nt * 8 + ec;
            float bx = bias[col], by = bias[col + 1];
            int r0 = row0 + wm * 64 + mt * 16 + er;
            float2 v0 = make_float2(acc[mt][nt][0] + bx, acc[mt][nt][1] + by);
            float2 v1 = make_float2(acc[mt][nt][2] + bx, acc[mt][nt][3] + by);
            *reinterpret_cast<float2*>(out + (size_t)r0 * NDIM + col) = v0;
            *reinterpret_cast<float2*>(out + (size_t)(r0 + 8) * NDIM + col) = v1;
        }
    }
}

// ---------------- launch ----------------
extern "C" void kernel_launch(void* const* d_in, const int* in_sizes, int n_in,
                              void* d_out, int out_size)
{
    const int*   x_ind = (const int*)  d_in[0];
    const float* embed = (const float*)d_in[1];
    const float* U_i   = (const float*)d_in[2];
    const float* U_f   = (const float*)d_in[3];
    const float* U_g   = (const float*)d_in[4];
    const float* U_o   = (const float*)d_in[5];
    const float* W_i   = (const float*)d_in[6];
    const float* W_f   = (const float*)d_in[7];
    const float* W_g   = (const float*)d_in[8];
    const float* W_o   = (const float*)d_in[9];
    const float* b_i   = (const float*)d_in[10];
    const float* b_f   = (const float*)d_in[11];
    const float* b_g   = (const float*)d_in[12];
    const float* b_o   = (const float*)d_in[13];
    const float* W_hy  = (const float*)d_in[14];
    const float* b_y   = (const float*)d_in[15];
    float* out = (float*)d_out;

    const int smem0 = NBUF * 3 * TILE_SB;   // MODE 0: 92160 B
    const int smem1 = NBUF * 2 * TILE_SB;   // MODE 1: 61440 B
    cudaFuncSetAttribute(hgemm_kernel<0>,
                         cudaFuncAttributeMaxDynamicSharedMemorySize, smem0);
    cudaFuncSetAttribute(hgemm_kernel<1>,
                         cudaFuncAttributeMaxDynamicSharedMemorySize, smem1);

    // 1. bias pack
    packb_kernel<<<(G_ + 255) / 256, 256>>>(b_i, b_f, b_g, b_o);

    // 2. weight conversions
    {
        dim3 grid(V_ / 32, H_ / 32);
        dim3 blk(32, 8);
        convW_kernel<<<grid, blk>>>(W_hy);
    }
    {
        dim3 grid(H_ / 32, E_ / 32, 4);
        dim3 blk(32, 8);
        convU_kernel<<<grid, blk>>>(U_i, U_f, U_g, U_o);
    }

    // 3. gather + split embedded inputs
    gatherX_kernel<<<T_ * B_, 128>>>(embed, x_ind);

    // 4. xproj = X @ U^T + bcat (2-term fp16)
    {
        dim3 grid(G_ / 128, (T_ * B_) / 128);  // (8, 32)
        hgemm_kernel<0><<<grid, 256, smem0>>>(nullptr, nullptr);
    }

    // 5. LSTM recurrence v7 (512 threads/CTA)
    lstm_scan_v7<<<(B_ / NB) * CL_C, SCAN_THREADS>>>(W_i, W_f, W_g, W_o);

    // 6. logits = hs @ W_hy + b_y (1-term fp16)
    {
        dim3 grid(V_ / 128, (B_ * T_) / 128);  // (250, 32)
        hgemm_kernel<1><<<grid, 256, smem1>>>(b_y, out);
    }
}

// round 17
// speedup vs baseline: 1.1148x; 1.1148x over previous
#include <cuda_runtime.h>
#include <cuda_fp16.h>
#include <math.h>
#include <stdint.h>

#define B_ 32
#define T_ 128
#define E_ 512
#define H_ 256
#define V_ 32000
#define G_ 1024  // 4*H

// ---------------- scratch (device globals; no allocations) ----------------
__device__ float g_bcat[G_];             // [4H]
__device__ float g_xproj[T_ * B_ * G_];  // [T][B][4H] 16 MB
__device__ __half g_Xhi[T_ * B_ * E_];   // gathered embed split (fp16), 4 MB
__device__ __half g_Xlo[T_ * B_ * E_];
__device__ __half g_Utf[G_ * E_];        // U^T single fp16, [G][E] 1 MB
__device__ __half g_Af[B_ * T_ * H_];    // hs single fp16, [B*T][H] 2 MB
__device__ __half g_Btf[V_ * H_];        // W_hy^T single fp16, [V][H] 16 MB

// ======================= PTX helpers (sm_90-base only) =====================
__device__ __forceinline__ uint32_t smem_u32(const void* p) {
    uint32_t a;
    asm("{ .reg .u64 t; cvta.to.shared.u64 t, %1; cvt.u32.u64 %0, t; }"
        : "=r"(a) : "l"(p));
    return a;
}

__device__ __forceinline__ void cp_async16(uint32_t saddr, const void* gaddr) {
    asm volatile("cp.async.cg.shared.global [%0], [%1], 16;"
                 :: "r"(saddr), "l"(gaddr) : "memory");
}
__device__ __forceinline__ void cp_commit() {
    asm volatile("cp.async.commit_group;" ::: "memory");
}
template <int N>
__device__ __forceinline__ void cp_wait() {
    asm volatile("cp.async.wait_group %0;" :: "n"(N) : "memory");
}

__device__ __forceinline__ void ldsm_x4(uint32_t& r0, uint32_t& r1,
                                        uint32_t& r2, uint32_t& r3, uint32_t a) {
    asm volatile("ldmatrix.sync.aligned.m8n8.x4.shared.b16 {%0,%1,%2,%3}, [%4];"
                 : "=r"(r0), "=r"(r1), "=r"(r2), "=r"(r3) : "r"(a));
}
__device__ __forceinline__ void ldsm_x2(uint32_t& r0, uint32_t& r1, uint32_t a) {
    asm volatile("ldmatrix.sync.aligned.m8n8.x2.shared.b16 {%0,%1}, [%2];"
                 : "=r"(r0), "=r"(r1) : "r"(a));
}

__device__ __forceinline__ void mma_f16(float* d, const uint32_t* a,
                                        const uint32_t* b) {
    asm volatile(
        "mma.sync.aligned.m16n8k16.row.col.f32.f16.f16.f32 "
        "{%0,%1,%2,%3}, {%4,%5,%6,%7}, {%8,%9}, {%0,%1,%2,%3};"
        : "+f"(d[0]), "+f"(d[1]), "+f"(d[2]), "+f"(d[3])
        : "r"(a[0]), "r"(a[1]), "r"(a[2]), "r"(a[3]), "r"(b[0]), "r"(b[1]));
}

#define CLUSTER_SYNC() do { \
    asm volatile("barrier.cluster.arrive.aligned;" ::: "memory"); \
    asm volatile("barrier.cluster.wait.aligned;" ::: "memory"); \
} while (0)

__device__ __forceinline__ uint32_t mapa_cluster(uint32_t local, uint32_t rank) {
    uint32_t r;
    asm volatile("mapa.shared::cluster.u32 %0, %1, %2;" : "=r"(r) : "r"(local), "r"(rank));
    return r;
}
__device__ __forceinline__ void st_cluster_f32(uint32_t addr, float v) {
    asm volatile("st.shared::cluster.f32 [%0], %1;" :: "r"(addr), "f"(v) : "memory");
}

// fast NaN-safe sigmoid / tanh via MUFU.EX2 (rel err ~2^-22)
__device__ __forceinline__ float fast_sigmoid(float x) {
    return 1.f / (1.f + __expf(-x));
}
__device__ __forceinline__ float fast_tanh(float x) {
    return 1.f - 2.f / (1.f + __expf(2.f * x));
}

// ============== fused prep: convW + convU + gatherX + packb =================
// grid ranges: [0,8000) convW tiles; [8000,8512) convU tiles;
//              [8512,12608) gatherX rows; [12608,12612) packb.
#define PREP_CTAS 12612

__global__ __launch_bounds__(256) void prep_kernel(
    const float* __restrict__ W_hy,
    const float* __restrict__ Ui, const float* __restrict__ Uf,
    const float* __restrict__ Ug, const float* __restrict__ Uo,
    const float* __restrict__ embed, const int* __restrict__ xind,
    const float* __restrict__ bi, const float* __restrict__ bf,
    const float* __restrict__ bg, const float* __restrict__ bo)
{
    const int bid = blockIdx.x;
    const int tid = threadIdx.x;
    const int tx = tid & 31, ty = tid >> 5;
    __shared__ float tl[32][33];

    if (bid < 8000) {
        // ---- convW: W_hy [H][V] -> Btf [V][H] fp16 ----
        int v0 = (bid % 1000) * 32, k0 = (bid / 1000) * 32;
#pragma unroll
        for (int i = 0; i < 4; i++) {
            int k = ty + i * 8;
            tl[k][tx] = W_hy[(size_t)(k0 + k) * V_ + v0 + tx];
        }
        __syncthreads();
#pragma unroll
        for (int i = 0; i < 4; i++) {
            int vr = ty + i * 8;
            g_Btf[(size_t)(v0 + vr) * H_ + k0 + tx] = __float2half(tl[tx][vr]);
        }
    } else if (bid < 8512) {
        // ---- convU: U [E][H] -> Utf [G][E] fp16 ----
        int b = bid - 8000;               // gate*128 + e_tile*8 + h_tile
        int gate = b >> 7;
        int rem  = b & 127;
        int h0 = (rem & 7) * 32;
        int e0 = (rem >> 3) * 32;
        const float* U = (gate == 0) ? Ui : (gate == 1) ? Uf
                        : (gate == 2) ? Ug : Uo;
#pragma unroll
        for (int i = 0; i < 4; i++) {
            int e = ty + i * 8;
            tl[e][tx] = U[(size_t)(e0 + e) * H_ + h0 + tx];
        }
        __syncthreads();
#pragma unroll
        for (int i = 0; i < 4; i++) {
            int hr = ty + i * 8;
            g_Utf[(size_t)(gate * H_ + h0 + hr) * E_ + e0 + tx] =
                __float2half(tl[tx][hr]);
        }
    } else if (bid < 12608) {
        // ---- gatherX: row r = t*B+b; 256 threads x 2 floats = E=512 ----
        int r = bid - 8512;
        int t = r / B_, b = r % B_;
        const float* src = embed + (size_t)xind[b * T_ + t] * E_;
        float2 v = *reinterpret_cast<const float2*>(src + tid * 2);
        __half h0 = __float2half(v.x);
        __half h1 = __float2half(v.y);
        __half2 hi = {h0, h1};
        __half2 lo = {__float2half(v.x - __half2float(h0)),
                      __float2half(v.y - __half2float(h1))};
        *reinterpret_cast<__half2*>(g_Xhi + (size_t)r * E_ + tid * 2) = hi;
        *reinterpret_cast<__half2*>(g_Xlo + (size_t)r * E_ + tid * 2) = lo;
    } else {
        // ---- packb ----
        int i = (bid - 12608) * 256 + tid;
        if (i < G_) {
            int g = i / H_, jj = i % H_;
            const float* bb = (g == 0) ? bi : (g == 1) ? bf
                             : (g == 2) ? bg : bo;
            g_bcat[i] = bb[jj];
        }
    }
}

// ===== LSTM recurrence v6 (R15 known-good: 256 thr, direct W, fast gates) ==
#define CL_C 8
#define NB 2

__global__ void __cluster_dims__(CL_C, 1, 1) __launch_bounds__(256, 1)
lstm_scan_v6(const float* __restrict__ Wi, const float* __restrict__ Wf,
             const float* __restrict__ Wg, const float* __restrict__ Wo)
{
    __shared__ float h_s[2 * NB * 256];     // [buf][batch][256]
    __shared__ float zp_s[8 * NB * 128];    // [kg][batch][col]

    const int tid = threadIdx.x;
    uint32_t rank;
    asm("mov.u32 %0, %%cluster_ctarank;" : "=r"(rank));
    const int cid = blockIdx.x / CL_C;

    const int kg = tid >> 5;          // 32-k block 0..7
    const int cg = tid & 31;          // 4-col group 0..31
    const int gate0 = cg >> 3;        // gate of these 4 cols
    const int s0    = (cg & 7) * 4;   // slice col base

    const float* wsel = (gate0 == 0) ? Wi : (gate0 == 1) ? Wf
                       : (gate0 == 2) ? Wg : Wo;
    float4 wreg[32];
    {
        const float* wp = wsel + (size_t)(kg * 32) * H_ + (int)rank * 32 + s0;
#pragma unroll
        for (int k = 0; k < 32; k++)
            wreg[k] = *reinterpret_cast<const float4*>(wp + (size_t)k * H_);
    }

    for (int i = tid; i < 2 * NB * 256; i += 256) h_s[i] = 0.f;
    CLUSTER_SYNC();

    const int bgl0 = cid * NB;

    const int gb = tid >> 5;   // batch (valid when tid<64)
    const int gs = tid & 31;   // slice col
    float c_reg = 0.f;

    for (int t = 0; t < T_; t++) {
        const int p = t & 1;

        float xpi = 0.f, xpf = 0.f, xpg = 0.f, xpo = 0.f;
        if (tid < 64) {
            const float* xb = g_xproj + (size_t)(t * B_ + bgl0 + gb) * G_ +
                              (int)rank * 32 + gs;
            xpi = xb[0];
            xpf = xb[H_];
            xpg = xb[2 * H_];
            xpo = xb[3 * H_];
        }

        const float* h0p = h_s + p * (NB * 256) + kg * 32;
        const float* h1p = h0p + 256;
        float4 a0 = make_float4(0.f, 0.f, 0.f, 0.f);
        float4 a1 = make_float4(0.f, 0.f, 0.f, 0.f);
#pragma unroll
        for (int i = 0; i < 8; i++) {
            float4 v0 = *reinterpret_cast<const float4*>(h0p + i * 4);
            float4 v1 = *reinterpret_cast<const float4*>(h1p + i * 4);
#pragma unroll
            for (int kk = 0; kk < 4; kk++) {
                float4 w = wreg[i * 4 + kk];
                float e0 = (kk == 0) ? v0.x : (kk == 1) ? v0.y : (kk == 2) ? v0.z : v0.w;
                float e1 = (kk == 0) ? v1.x : (kk == 1) ? v1.y : (kk == 2) ? v1.z : v1.w;
                a0.x += e0 * w.x; a0.y += e0 * w.y; a0.z += e0 * w.z; a0.w += e0 * w.w;
                a1.x += e1 * w.x; a1.y += e1 * w.y; a1.z += e1 * w.z; a1.w += e1 * w.w;
            }
        }
        *reinterpret_cast<float4*>(zp_s + (kg * NB + 0) * 128 + cg * 4) = a0;
        *reinterpret_cast<float4*>(zp_s + (kg * NB + 1) * 128 + cg * 4) = a1;
        __syncthreads();

        if (tid < 64) {
            float zi = xpi, zf = xpf, zg = xpg, zo = xpo;
#pragma unroll
            for (int q = 0; q < 8; q++) {
                const float* base = zp_s + (q * NB + gb) * 128;
                zi += base[gs];
                zf += base[32 + gs];
                zg += base[64 + gs];
                zo += base[96 + gs];
            }
            float ig = fast_sigmoid(zi);
            float fg = fast_sigmoid(zf);
            float gv = fast_tanh(zg);
            float og = fast_sigmoid(zo);
            c_reg = fg * c_reg + ig * gv;
            float h = og * fast_tanh(c_reg);

            int bg = bgl0 + gb;
            g_Af[((size_t)bg * T_ + t) * H_ + rank * 32 + gs] = __float2half(h);

            const int q2 = p ^ 1;
            uint32_t la = smem_u32(h_s + q2 * (NB * 256) + gb * 256 +
                                   (int)rank * 32 + gs);
#pragma unroll
            for (int rk = 0; rk < CL_C; rk++)
                st_cluster_f32(mapa_cluster(la, (uint32_t)rk), h);
        }
        CLUSTER_SYNC();
    }
}

// ======== HGEMM fp16, cp.async ring (NBUF 3 for MODE0, 4 for MODE1) ========
// MODE 0 (2-term A): g_xproj = (Xhi+Xlo) @ Utf^T + g_bcat   (K=512)
// MODE 1 (1-term A): out     = Af @ Btf^T + b_y             (K=256)
// BM=BN=128, BK=32, 8 warps 2x4, m16n8k16 f16, occ 2.
#define BK 32
#define SROW 40                       // padded row stride (fp16 elems) = 80B
#define TILE_SB (128 * SROW * 2)      // 10240 B per matrix per stage

template <int MODE>
__global__ __launch_bounds__(256, 2) void hgemm_kernel(
    const float* __restrict__ bias_ext, float* __restrict__ out_ext)
{
    constexpr int NDIM = (MODE == 0) ? G_ : V_;
    constexpr int KDIM = (MODE == 0) ? E_ : H_;
    constexpr int NSTG = KDIM / BK;
    constexpr int NA   = (MODE == 0) ? 2 : 1;        // A terms
    constexpr int NMAT = NA + 1;
    constexpr int NBUFM = (MODE == 0) ? 3 : 4;       // ring depth
    constexpr int STG  = NMAT * TILE_SB;             // stage bytes

    extern __shared__ char smem[];
    const uint32_t sb = smem_u32(smem);
    const int tid  = threadIdx.x;
    const int lane = tid & 31;
    const int wid  = tid >> 5;
    const int wm   = wid >> 2;
    const int wn   = wid & 3;

    const int row0 = blockIdx.y * 128;
    const int col0 = blockIdx.x * 128;

    const float* bias = (MODE == 0) ? g_bcat  : bias_ext;
    float*       out  = (MODE == 0) ? g_xproj : out_ext;

    const int ld_r   = tid >> 2;
    const int ld_seg = tid & 3;
    const __half* gsrc[NMAT];
    if (MODE == 0) {
        gsrc[0] = g_Xhi + (size_t)row0 * KDIM;
        gsrc[1] = g_Xlo + (size_t)row0 * KDIM;
        gsrc[NA] = g_Utf + (size_t)col0 * KDIM;
    } else {
        gsrc[0] = g_Af + (size_t)row0 * KDIM;
        gsrc[NA] = g_Btf + (size_t)col0 * KDIM;
    }

    float acc[4][4][4];
#pragma unroll
    for (int i = 0; i < 4; i++)
#pragma unroll
        for (int j = 0; j < 4; j++)
#pragma unroll
            for (int r = 0; r < 4; r++) acc[i][j][r] = 0.f;

    // prologue: stages 0 .. NBUFM-2
#pragma unroll
    for (int ps = 0; ps < NBUFM - 1; ps++) {
#pragma unroll
        for (int m = 0; m < NMAT; m++)
#pragma unroll
            for (int h = 0; h < 2; h++) {
                int r = ld_r + h * 64;
                uint32_t sa = sb + ps * STG + m * TILE_SB +
                              r * (SROW * 2) + ld_seg * 16;
                cp_async16(sa, gsrc[m] + (size_t)r * KDIM + ps * BK + ld_seg * 8);
            }
        cp_commit();
    }

    for (int s = 0; s < NSTG; s++) {
        if (s + 1 < NSTG) cp_wait<NBUFM - 2>(); else cp_wait<0>();
        __syncthreads();

        if (s + NBUFM - 1 < NSTG) {
            uint32_t bufo = (uint32_t)((s + NBUFM - 1) % NBUFM) * STG;
            int kofs = (s + NBUFM - 1) * BK;
#pragma unroll
            for (int m = 0; m < NMAT; m++)
#pragma unroll
                for (int h = 0; h < 2; h++) {
                    int r = ld_r + h * 64;
                    uint32_t sa = sb + bufo + m * TILE_SB +
                                  r * (SROW * 2) + ld_seg * 16;
                    cp_async16(sa, gsrc[m] + (size_t)r * KDIM + kofs + ld_seg * 8);
                }
            cp_commit();
        }

        const uint32_t base = sb + (uint32_t)(s % NBUFM) * STG;
        const uint32_t sA0 = base;
        const uint32_t sA1 = base + TILE_SB;             // valid when NA==2
        const uint32_t sBf = base + NA * TILE_SB;

#pragma unroll
        for (int kk = 0; kk < 2; kk++) {
            uint32_t bf[4][2];
            const int b_row_l = (lane & 7);
            const int b_col   = kk * 16 + ((lane >> 3) & 1) * 8;
#pragma unroll
            for (int nt = 0; nt < 4; nt++) {
                int r = wn * 32 + nt * 8 + b_row_l;
                uint32_t off = (uint32_t)(r * (SROW * 2) + b_col * 2);
                ldsm_x2(bf[nt][0], bf[nt][1], sBf + off);
            }
            const int a_row_l = (lane & 15);
            const int a_col   = kk * 16 + (lane >> 4) * 8;
#pragma unroll
            for (int mt = 0; mt < 4; mt++) {
                int r = wm * 64 + mt * 16 + a_row_l;
                uint32_t off = (uint32_t)(r * (SROW * 2) + a_col * 2);
                uint32_t a0[4];
                ldsm_x4(a0[0], a0[1], a0[2], a0[3], sA0 + off);
                if (NA == 2) {
                    uint32_t a1[4];
                    ldsm_x4(a1[0], a1[1], a1[2], a1[3], sA1 + off);
#pragma unroll
                    for (int nt = 0; nt < 4; nt++) {
                        mma_f16(acc[mt][nt], a0, bf[nt]);
                        mma_f16(acc[mt][nt], a1, bf[nt]);
                    }
                } else {
#pragma unroll
                    for (int nt = 0; nt < 4; nt++)
                        mma_f16(acc[mt][nt], a0, bf[nt]);
                }
            }
        }
    }

    __syncthreads();
    const int er = lane >> 2;
    const int ec = (lane & 3) * 2;
#pragma unroll
    for (int mt = 0; mt < 4; mt++) {
#pragma unroll
        for (int nt = 0; nt < 4; nt++) {
            int col = col0 + wn * 32 + nt * 8 + ec;
            float bx = bias[col], by = bias[col + 1];
            int r0 = row0 + wm * 64 + mt * 16 + er;
            float2 v0 = make_float2(acc[mt][nt][0] + bx, acc[mt][nt][1] + by);
            float2 v1 = make_float2(acc[mt][nt][2] + bx, acc[mt][nt][3] + by);
            *reinterpret_cast<float2*>(out + (size_t)r0 * NDIM + col) = v0;
            *reinterpret_cast<float2*>(out + (size_t)(r0 + 8) * NDIM + col) = v1;
        }
    }
}

// ---------------- launch ----------------
extern "C" void kernel_launch(void* const* d_in, const int* in_sizes, int n_in,
                              void* d_out, int out_size)
{
    const int*   x_ind = (const int*)  d_in[0];
    const float* embed = (const float*)d_in[1];
    const float* U_i   = (const float*)d_in[2];
    const float* U_f   = (const float*)d_in[3];
    const float* U_g   = (const float*)d_in[4];
    const float* U_o   = (const float*)d_in[5];
    const float* W_i   = (const float*)d_in[6];
    const float* W_f   = (const float*)d_in[7];
    const float* W_g   = (const float*)d_in[8];
    const float* W_o   = (const float*)d_in[9];
    const float* b_i   = (const float*)d_in[10];
    const float* b_f   = (const float*)d_in[11];
    const float* b_g   = (const float*)d_in[12];
    const float* b_o   = (const float*)d_in[13];
    const float* W_hy  = (const float*)d_in[14];
    const float* b_y   = (const float*)d_in[15];
    float* out = (float*)d_out;

    const int smem0 = 3 * 3 * TILE_SB;   // MODE 0: NBUF3 x 3 mats = 92160 B
    const int smem1 = 4 * 2 * TILE_SB;   // MODE 1: NBUF4 x 2 mats = 81920 B
    cudaFuncSetAttribute(hgemm_kernel<0>,
                         cudaFuncAttributeMaxDynamicSharedMemorySize, smem0);
    cudaFuncSetAttribute(hgemm_kernel<1>,
                         cudaFuncAttributeMaxDynamicSharedMemorySize, smem1);

    // 1. fused prep: convW + convU + gatherX + packb
    prep_kernel<<<PREP_CTAS, 256>>>(W_hy, U_i, U_f, U_g, U_o,
                                    embed, x_ind, b_i, b_f, b_g, b_o);

    // 2. xproj = X @ U^T + bcat (2-term fp16)
    {
        dim3 grid(G_ / 128, (T_ * B_) / 128);  // (8, 32)
        hgemm_kernel<0><<<grid, 256, smem0>>>(nullptr, nullptr);
    }

    // 3. LSTM recurrence v6
    lstm_scan_v6<<<(B_ / NB) * CL_C, 256>>>(W_i, W_f, W_g, W_o);

    // 4. logits = hs @ W_hy + b_y (1-term fp16)
    {
        dim3 grid(V_ / 128, (B_ * T_) / 128);  // (250, 32)
        hgemm_kernel<1><<<grid, 256, smem1>>>(b_y, out);
    }
}